// round 10
// baseline (speedup 1.0000x reference)
#include <cuda_runtime.h>
#include <cstdint>

#define NN 50000
#define NE 800000
#define DD 128
#define NBLK 196   // ceil(50000/256)

// ------------------------- device scratch (no allocs) -----------------------
__device__ float  g_accum[NN * DD];  // aggregated messages (sum)
__device__ float  g_cnt[NN];         // in-degree (float, for GEMM1 fusion)
__device__ float  g_h[NN * DD];      // after GEMM1 + relu
__device__ int    g_deg[NN];
__device__ int    g_off[NN];         // exclusive offsets
__device__ int    g_wptr[NN];        // fill cursors (init = g_off)
__device__ float2 g_edges[NE];       // (src as int-bits, attr) in CSR order
__device__ int    g_bsum[NBLK];
__device__ int    g_boff[NBLK];

// ---- packed f32x2 helpers (base PTX ISA, sm_100+; not 'a'-gated) -----------
__device__ __forceinline__ unsigned long long pack2(float lo, float hi) {
    unsigned long long r;
    asm("mov.b64 %0, {%1, %2};" : "=l"(r) : "f"(lo), "f"(hi));
    return r;
}
__device__ __forceinline__ void unpack2(float& lo, float& hi, unsigned long long v) {
    asm("mov.b64 {%0, %1}, %2;" : "=f"(lo), "=f"(hi) : "l"(v));
}
__device__ __forceinline__ void ffma2(unsigned long long& d, unsigned long long a,
                                      unsigned long long b) {
    asm("fma.rn.f32x2 %0, %1, %2, %0;" : "+l"(d) : "l"(a), "l"(b));
}

// ---------------------------------------------------------------------------
// CSR build
// ---------------------------------------------------------------------------
__global__ void zero_deg_kernel() {
    int i = blockIdx.x * blockDim.x + threadIdx.x;
    if (i < NN) g_deg[i] = 0;
}

__global__ void hist_kernel(const int* __restrict__ edge_index) {
    int e = blockIdx.x * blockDim.x + threadIdx.x;
    if (e < NE) atomicAdd(&g_deg[__ldg(&edge_index[NE + e])], 1);
}

__global__ void bsum_kernel() {
    __shared__ int s[256];
    int t = threadIdx.x;
    int i = blockIdx.x * 256 + t;
    s[t] = (i < NN) ? g_deg[i] : 0;
    __syncthreads();
    for (int off = 128; off > 0; off >>= 1) {
        if (t < off) s[t] += s[t + off];
        __syncthreads();
    }
    if (t == 0) g_bsum[blockIdx.x] = s[0];
}

// parallel exclusive scan of 196 block sums (single block, smem scan)
__global__ void scan_bsum_kernel() {
    __shared__ int s[256];
    int t = threadIdx.x;
    int v = (t < NBLK) ? g_bsum[t] : 0;
    s[t] = v;
    __syncthreads();
    for (int off = 1; off < 256; off <<= 1) {
        int x = (t >= off) ? s[t - off] : 0;
        __syncthreads();
        s[t] += x;
        __syncthreads();
    }
    if (t < NBLK) g_boff[t] = s[t] - v;
}

__global__ void block_scan_kernel() {
    __shared__ int s[256];
    int t = threadIdx.x;
    int i = blockIdx.x * 256 + t;
    int v = (i < NN) ? g_deg[i] : 0;
    s[t] = v;
    __syncthreads();
    for (int off = 1; off < 256; off <<= 1) {
        int x = (t >= off) ? s[t - off] : 0;
        __syncthreads();
        s[t] += x;
        __syncthreads();
    }
    if (i < NN) {
        int excl = s[t] - v + g_boff[blockIdx.x];
        g_off[i]  = excl;
        g_wptr[i] = excl;
    }
}

// fill: store packed (src, attr) directly in CSR slot (kills the eid chain)
__global__ void fill_kernel(const int* __restrict__ edge_index,
                            const float* __restrict__ edge_attr) {
    int e = blockIdx.x * blockDim.x + threadIdx.x;
    if (e < NE) {
        int dst = __ldg(&edge_index[NE + e]);
        int src = __ldg(&edge_index[e]);
        float a = __ldg(&edge_attr[e]);
        int pos = atomicAdd(&g_wptr[dst], 1);
        g_edges[pos] = make_float2(__int_as_float(src), a);
    }
}

// ---------------------------------------------------------------------------
// Gather: one warp per dst node; prefetch-2 double buffer over packed edges.
// ---------------------------------------------------------------------------
__global__ void gather_kernel(const float* __restrict__ hidden,
                              const float* __restrict__ We,
                              const float* __restrict__ be) {
    int gtid = blockIdx.x * blockDim.x + threadIdx.x;
    int n = gtid >> 5, lane = gtid & 31;
    if (n >= NN) return;

    int deg  = g_deg[n];
    int base = g_off[n];
    int d0   = lane * 4;

    float4 w = *(const float4*)&We[d0];
    float4 b = *(const float4*)&be[d0];
    float4 acc = make_float4(0.f, 0.f, 0.f, 0.f);

    int   sbuf[2] = {0, 0};
    float abuf[2] = {0.f, 0.f};
#pragma unroll
    for (int p = 0; p < 2; p++) {
        if (p < deg) {
            float2 ed = __ldg(&g_edges[base + p]);
            sbuf[p] = __float_as_int(ed.x);
            abuf[p] = ed.y;
        }
    }

    for (int j = 0; j < deg; j++) {
        int   src = sbuf[j & 1];
        float a   = abuf[j & 1];
        float4 h  = *(const float4*)&hidden[(size_t)src * DD + d0];
        if (j + 2 < deg) {
            float2 ed = __ldg(&g_edges[base + j + 2]);
            sbuf[j & 1] = __float_as_int(ed.x);
            abuf[j & 1] = ed.y;
        }
        acc.x += fmaxf(fmaf(a, w.x, b.x) + h.x, 0.f);
        acc.y += fmaxf(fmaf(a, w.y, b.y) + h.y, 0.f);
        acc.z += fmaxf(fmaf(a, w.z, b.z) + h.z, 0.f);
        acc.w += fmaxf(fmaf(a, w.w, b.w) + h.w, 0.f);
    }

    *(float4*)&g_accum[(size_t)n * DD + d0] = acc;
    if (lane == 0) g_cnt[n] = (float)deg;
}

// ---------------------------------------------------------------------------
// GEMMs: TILE_M=128, 256 threads, 16 rows/warp as 8 f32x2 row-pairs.
// Inner loop: 32 FFMA2 per kk (density 32/45). FUSED finalize in A loader.
// ---------------------------------------------------------------------------
template <bool FUSED, bool RELU>
__global__ void gemm128_kernel(const float* __restrict__ Ain,
                               const float* __restrict__ eps,
                               const float* __restrict__ W,
                               const float* __restrict__ bias,
                               float* __restrict__ C, int M) {
    __shared__ float As2[32][130];    // k-major A tile (128 rows, pad 130)
    __shared__ float Ws[32][128];

    int tid  = threadIdx.x;
    int warp = tid >> 5;
    int lane = tid & 31;
    int row0 = blockIdx.x * 128;
    int r0   = warp * 16;
    int c0   = lane * 4;

    float s = FUSED ? (1.0f + __ldg(&eps[0])) : 0.f;

    unsigned long long acc[8][4];
#pragma unroll
    for (int p = 0; p < 8; p++)
#pragma unroll
        for (int c = 0; c < 4; c++) acc[p][c] = 0ull;

    for (int kt = 0; kt < 4; kt++) {
        // A tile: 128 rows x 32 k (1024 float4), transposed store
#pragma unroll
        for (int idx = tid; idx < 1024; idx += 256) {
            int r = idx >> 3, f = idx & 7;
            int grow = row0 + r;
            float4 v = make_float4(0.f, 0.f, 0.f, 0.f);
            if (grow < M) {
                size_t off = (size_t)grow * DD + kt * 32 + f * 4;
                v = *(const float4*)&Ain[off];
                if (FUSED) {
                    float inv = 1.0f / fmaxf(g_cnt[grow], 1.0f);
                    float4 a = *(const float4*)&g_accum[off];
                    v.x = fmaf(s, v.x, a.x * inv);
                    v.y = fmaf(s, v.y, a.y * inv);
                    v.z = fmaf(s, v.z, a.z * inv);
                    v.w = fmaf(s, v.w, a.w * inv);
                }
            }
            As2[f * 4 + 0][r] = v.x;
            As2[f * 4 + 1][r] = v.y;
            As2[f * 4 + 2][r] = v.z;
            As2[f * 4 + 3][r] = v.w;
        }
        // W tile: 32 k-rows x 128 cols
#pragma unroll
        for (int idx = tid; idx < 1024; idx += 256) {
            int r = idx >> 5, f = idx & 31;
            *(float4*)&Ws[r][f * 4] = *(const float4*)&W[(kt * 32 + r) * DD + f * 4];
        }
        __syncthreads();

#pragma unroll
        for (int kk = 0; kk < 32; kk++) {
            float4 bv = *(float4*)&Ws[kk][c0];
            unsigned long long bb[4];
            bb[0] = pack2(bv.x, bv.x);
            bb[1] = pack2(bv.y, bv.y);
            bb[2] = pack2(bv.z, bv.z);
            bb[3] = pack2(bv.w, bv.w);
#pragma unroll
            for (int p = 0; p < 8; p++) {
                unsigned long long a2 =
                    *(const unsigned long long*)&As2[kk][r0 + 2 * p];
                ffma2(acc[p][0], a2, bb[0]);
                ffma2(acc[p][1], a2, bb[1]);
                ffma2(acc[p][2], a2, bb[2]);
                ffma2(acc[p][3], a2, bb[3]);
            }
        }
        __syncthreads();
    }

    float4 bb4 = *(const float4*)&bias[c0];
#pragma unroll
    for (int p = 0; p < 8; p++) {
        float lo[4], hi[4];
#pragma unroll
        for (int c = 0; c < 4; c++) unpack2(lo[c], hi[c], acc[p][c]);

        int rA = row0 + r0 + 2 * p;
        if (rA < M) {
            float4 o;
            o.x = lo[0] + bb4.x; o.y = lo[1] + bb4.y;
            o.z = lo[2] + bb4.z; o.w = lo[3] + bb4.w;
            if (RELU) {
                o.x = fmaxf(o.x, 0.f); o.y = fmaxf(o.y, 0.f);
                o.z = fmaxf(o.z, 0.f); o.w = fmaxf(o.w, 0.f);
            }
            *(float4*)&C[(size_t)rA * DD + c0] = o;
        }
        int rB = rA + 1;
        if (rB < M) {
            float4 o;
            o.x = hi[0] + bb4.x; o.y = hi[1] + bb4.y;
            o.z = hi[2] + bb4.z; o.w = hi[3] + bb4.w;
            if (RELU) {
                o.x = fmaxf(o.x, 0.f); o.y = fmaxf(o.y, 0.f);
                o.z = fmaxf(o.z, 0.f); o.w = fmaxf(o.w, 0.f);
            }
            *(float4*)&C[(size_t)rB * DD + c0] = o;
        }
    }
}

// ---------------------------------------------------------------------------
extern "C" void kernel_launch(void* const* d_in, const int* in_sizes, int n_in,
                              void* d_out, int out_size) {
    const float* hidden = (const float*)d_in[0];
    const int*   eidx   = (const int*)d_in[1];
    const float* eattr  = (const float*)d_in[2];
    const float* We     = (const float*)d_in[3];
    const float* be     = (const float*)d_in[4];
    const float* W1     = (const float*)d_in[5];
    const float* b1     = (const float*)d_in[6];
    const float* W2     = (const float*)d_in[7];
    const float* b2     = (const float*)d_in[8];
    const float* eps    = (const float*)d_in[9];
    float*       out    = (float*)d_out;

    // DEVICE address of g_h (host &g_h is the ATS-readable shadow symbol!)
    float* p_h = nullptr;
    cudaGetSymbolAddress((void**)&p_h, g_h);

    // --- CSR build ---
    zero_deg_kernel<<<NBLK, 256>>>();
    hist_kernel<<<(NE + 255) / 256, 256>>>(eidx);
    bsum_kernel<<<NBLK, 256>>>();
    scan_bsum_kernel<<<1, 256>>>();
    block_scan_kernel<<<NBLK, 256>>>();
    fill_kernel<<<(NE + 255) / 256, 256>>>(eidx, eattr);

    // --- gather (no float atomics) ---
    gather_kernel<<<(NN * 32 + 255) / 256, 256>>>(hidden, We, be);

    // --- MLP ---
    int gblocks = (NN + 127) / 128;   // 391
    gemm128_kernel<true,  true ><<<gblocks, 256>>>(hidden, eps, W1, b1, p_h, NN);
    gemm128_kernel<false, false><<<gblocks, 256>>>(p_h,    eps, W2, b2, out, NN);
}

// round 11
// speedup vs baseline: 1.1552x; 1.1552x over previous
#include <cuda_runtime.h>
#include <cstdint>

#define NN 50000
#define NE 800000
#define DD 128
#define NBLK 196   // ceil(50000/256)

// ------------------------- device scratch (no allocs) -----------------------
__device__ float  g_accum[NN * DD];  // aggregated messages (sum)
__device__ float  g_cnt[NN];         // in-degree (float, for GEMM1 fusion)
__device__ float  g_h[NN * DD];      // after GEMM1 + relu
__device__ int    g_deg[NN];
__device__ int    g_off[NN];         // exclusive offsets
__device__ int    g_wptr[NN];        // fill cursors (init = g_off)
__device__ float2 g_edges[NE];       // (src as int-bits, attr) in CSR order
__device__ int    g_bsum[NBLK];
__device__ int    g_boff[NBLK];

// ---- packed f32x2 helpers (base PTX ISA, sm_100+; not 'a'-gated) -----------
__device__ __forceinline__ unsigned long long pack2(float lo, float hi) {
    unsigned long long r;
    asm("mov.b64 %0, {%1, %2};" : "=l"(r) : "f"(lo), "f"(hi));
    return r;
}
__device__ __forceinline__ void unpack2(float& lo, float& hi, unsigned long long v) {
    asm("mov.b64 {%0, %1}, %2;" : "=f"(lo), "=f"(hi) : "l"(v));
}
__device__ __forceinline__ void ffma2(unsigned long long& d, unsigned long long a,
                                      unsigned long long b) {
    asm("fma.rn.f32x2 %0, %1, %2, %0;" : "+l"(d) : "l"(a), "l"(b));
}

// ---------------------------------------------------------------------------
// CSR build
// ---------------------------------------------------------------------------
__global__ void zero_deg_kernel() {
    int i = blockIdx.x * blockDim.x + threadIdx.x;
    if (i < NN) g_deg[i] = 0;
}

__global__ void hist_kernel(const int* __restrict__ edge_index) {
    int e = blockIdx.x * blockDim.x + threadIdx.x;
    if (e < NE) atomicAdd(&g_deg[__ldg(&edge_index[NE + e])], 1);
}

__global__ void bsum_kernel() {
    __shared__ int s[256];
    int t = threadIdx.x;
    int i = blockIdx.x * 256 + t;
    s[t] = (i < NN) ? g_deg[i] : 0;
    __syncthreads();
    for (int off = 128; off > 0; off >>= 1) {
        if (t < off) s[t] += s[t + off];
        __syncthreads();
    }
    if (t == 0) g_bsum[blockIdx.x] = s[0];
}

// parallel exclusive scan of 196 block sums (single block, smem scan)
__global__ void scan_bsum_kernel() {
    __shared__ int s[256];
    int t = threadIdx.x;
    int v = (t < NBLK) ? g_bsum[t] : 0;
    s[t] = v;
    __syncthreads();
    for (int off = 1; off < 256; off <<= 1) {
        int x = (t >= off) ? s[t - off] : 0;
        __syncthreads();
        s[t] += x;
        __syncthreads();
    }
    if (t < NBLK) g_boff[t] = s[t] - v;
}

__global__ void block_scan_kernel() {
    __shared__ int s[256];
    int t = threadIdx.x;
    int i = blockIdx.x * 256 + t;
    int v = (i < NN) ? g_deg[i] : 0;
    s[t] = v;
    __syncthreads();
    for (int off = 1; off < 256; off <<= 1) {
        int x = (t >= off) ? s[t - off] : 0;
        __syncthreads();
        s[t] += x;
        __syncthreads();
    }
    if (i < NN) {
        int excl = s[t] - v + g_boff[blockIdx.x];
        g_off[i]  = excl;
        g_wptr[i] = excl;
    }
}

// fill: store packed (src, attr) directly in CSR slot (kills the eid chain)
__global__ void fill_kernel(const int* __restrict__ edge_index,
                            const float* __restrict__ edge_attr) {
    int e = blockIdx.x * blockDim.x + threadIdx.x;
    if (e < NE) {
        int dst = __ldg(&edge_index[NE + e]);
        int src = __ldg(&edge_index[e]);
        float a = __ldg(&edge_attr[e]);
        int pos = atomicAdd(&g_wptr[dst], 1);
        g_edges[pos] = make_float2(__int_as_float(src), a);
    }
}

// ---------------------------------------------------------------------------
// Gather: one warp per dst node; prefetch-2 double buffer over packed edges.
// ---------------------------------------------------------------------------
__global__ void gather_kernel(const float* __restrict__ hidden,
                              const float* __restrict__ We,
                              const float* __restrict__ be) {
    int gtid = blockIdx.x * blockDim.x + threadIdx.x;
    int n = gtid >> 5, lane = gtid & 31;
    if (n >= NN) return;

    int deg  = g_deg[n];
    int base = g_off[n];
    int d0   = lane * 4;

    float4 w = *(const float4*)&We[d0];
    float4 b = *(const float4*)&be[d0];
    float4 acc = make_float4(0.f, 0.f, 0.f, 0.f);

    int   sbuf[2] = {0, 0};
    float abuf[2] = {0.f, 0.f};
#pragma unroll
    for (int p = 0; p < 2; p++) {
        if (p < deg) {
            float2 ed = __ldg(&g_edges[base + p]);
            sbuf[p] = __float_as_int(ed.x);
            abuf[p] = ed.y;
        }
    }

    for (int j = 0; j < deg; j++) {
        int   src = sbuf[j & 1];
        float a   = abuf[j & 1];
        float4 h  = *(const float4*)&hidden[(size_t)src * DD + d0];
        if (j + 2 < deg) {
            float2 ed = __ldg(&g_edges[base + j + 2]);
            sbuf[j & 1] = __float_as_int(ed.x);
            abuf[j & 1] = ed.y;
        }
        acc.x += fmaxf(fmaf(a, w.x, b.x) + h.x, 0.f);
        acc.y += fmaxf(fmaf(a, w.y, b.y) + h.y, 0.f);
        acc.z += fmaxf(fmaf(a, w.z, b.z) + h.z, 0.f);
        acc.w += fmaxf(fmaf(a, w.w, b.w) + h.w, 0.f);
    }

    *(float4*)&g_accum[(size_t)n * DD + d0] = acc;
    if (lane == 0) g_cnt[n] = (float)deg;
}

// ---------------------------------------------------------------------------
// GEMMs: TILE_M=64, 256 threads, 8 rows/warp as 4 f32x2 row-pairs (R7 config,
// regs=74, 43.5us measured). FUSED finalize in A loader.
// ---------------------------------------------------------------------------
template <bool FUSED, bool RELU>
__global__ void gemm128_kernel(const float* __restrict__ Ain,
                               const float* __restrict__ eps,
                               const float* __restrict__ W,
                               const float* __restrict__ bias,
                               float* __restrict__ C, int M) {
    __shared__ float As2[32][66];
    __shared__ float Ws[32][128];

    int tid  = threadIdx.x;
    int warp = tid >> 5;
    int lane = tid & 31;
    int row0 = blockIdx.x * 64;
    int r0   = warp * 8;
    int c0   = lane * 4;

    float s = FUSED ? (1.0f + __ldg(&eps[0])) : 0.f;

    unsigned long long acc[4][4];
#pragma unroll
    for (int p = 0; p < 4; p++)
#pragma unroll
        for (int c = 0; c < 4; c++) acc[p][c] = 0ull;

    for (int kt = 0; kt < 4; kt++) {
#pragma unroll
        for (int idx = tid; idx < 512; idx += 256) {
            int r = idx >> 3, f = idx & 7;
            int grow = row0 + r;
            float4 v = make_float4(0.f, 0.f, 0.f, 0.f);
            if (grow < M) {
                size_t off = (size_t)grow * DD + kt * 32 + f * 4;
                v = *(const float4*)&Ain[off];
                if (FUSED) {
                    float inv = 1.0f / fmaxf(g_cnt[grow], 1.0f);
                    float4 a = *(const float4*)&g_accum[off];
                    v.x = fmaf(s, v.x, a.x * inv);
                    v.y = fmaf(s, v.y, a.y * inv);
                    v.z = fmaf(s, v.z, a.z * inv);
                    v.w = fmaf(s, v.w, a.w * inv);
                }
            }
            As2[f * 4 + 0][r] = v.x;
            As2[f * 4 + 1][r] = v.y;
            As2[f * 4 + 2][r] = v.z;
            As2[f * 4 + 3][r] = v.w;
        }
#pragma unroll
        for (int idx = tid; idx < 1024; idx += 256) {
            int r = idx >> 5, f = idx & 31;
            *(float4*)&Ws[r][f * 4] = *(const float4*)&W[(kt * 32 + r) * DD + f * 4];
        }
        __syncthreads();

#pragma unroll
        for (int kk = 0; kk < 32; kk++) {
            float4 bv = *(float4*)&Ws[kk][c0];
            unsigned long long bb[4];
            bb[0] = pack2(bv.x, bv.x);
            bb[1] = pack2(bv.y, bv.y);
            bb[2] = pack2(bv.z, bv.z);
            bb[3] = pack2(bv.w, bv.w);
#pragma unroll
            for (int p = 0; p < 4; p++) {
                unsigned long long a2 =
                    *(const unsigned long long*)&As2[kk][r0 + 2 * p];
                ffma2(acc[p][0], a2, bb[0]);
                ffma2(acc[p][1], a2, bb[1]);
                ffma2(acc[p][2], a2, bb[2]);
                ffma2(acc[p][3], a2, bb[3]);
            }
        }
        __syncthreads();
    }

    float4 bb4 = *(const float4*)&bias[c0];
#pragma unroll
    for (int p = 0; p < 4; p++) {
        float lo[4], hi[4];
#pragma unroll
        for (int c = 0; c < 4; c++) unpack2(lo[c], hi[c], acc[p][c]);

        int rA = row0 + r0 + 2 * p;
        if (rA < M) {
            float4 o;
            o.x = lo[0] + bb4.x; o.y = lo[1] + bb4.y;
            o.z = lo[2] + bb4.z; o.w = lo[3] + bb4.w;
            if (RELU) {
                o.x = fmaxf(o.x, 0.f); o.y = fmaxf(o.y, 0.f);
                o.z = fmaxf(o.z, 0.f); o.w = fmaxf(o.w, 0.f);
            }
            *(float4*)&C[(size_t)rA * DD + c0] = o;
        }
        int rB = rA + 1;
        if (rB < M) {
            float4 o;
            o.x = hi[0] + bb4.x; o.y = hi[1] + bb4.y;
            o.z = hi[2] + bb4.z; o.w = hi[3] + bb4.w;
            if (RELU) {
                o.x = fmaxf(o.x, 0.f); o.y = fmaxf(o.y, 0.f);
                o.z = fmaxf(o.z, 0.f); o.w = fmaxf(o.w, 0.f);
            }
            *(float4*)&C[(size_t)rB * DD + c0] = o;
        }
    }
}

// ---------------------------------------------------------------------------
extern "C" void kernel_launch(void* const* d_in, const int* in_sizes, int n_in,
                              void* d_out, int out_size) {
    const float* hidden = (const float*)d_in[0];
    const int*   eidx   = (const int*)d_in[1];
    const float* eattr  = (const float*)d_in[2];
    const float* We     = (const float*)d_in[3];
    const float* be     = (const float*)d_in[4];
    const float* W1     = (const float*)d_in[5];
    const float* b1     = (const float*)d_in[6];
    const float* W2     = (const float*)d_in[7];
    const float* b2     = (const float*)d_in[8];
    const float* eps    = (const float*)d_in[9];
    float*       out    = (float*)d_out;

    // DEVICE address of g_h (host &g_h is the ATS-readable shadow symbol!)
    float* p_h = nullptr;
    cudaGetSymbolAddress((void**)&p_h, g_h);

    // --- CSR build ---
    zero_deg_kernel<<<NBLK, 256>>>();
    hist_kernel<<<(NE + 255) / 256, 256>>>(eidx);
    bsum_kernel<<<NBLK, 256>>>();
    scan_bsum_kernel<<<1, 256>>>();
    block_scan_kernel<<<NBLK, 256>>>();
    fill_kernel<<<(NE + 255) / 256, 256>>>(eidx, eattr);

    // --- gather (no float atomics) ---
    gather_kernel<<<(NN * 32 + 255) / 256, 256>>>(hidden, We, be);

    // --- MLP ---
    int gblocks = (NN + 63) / 64;   // 782
    gemm128_kernel<true,  true ><<<gblocks, 256>>>(hidden, eps, W1, b1, p_h, NN);
    gemm128_kernel<false, false><<<gblocks, 256>>>(p_h,    eps, W2, b2, out, NN);
}